// round 8
// baseline (speedup 1.0000x reference)
#include <cuda_runtime.h>
#include <math.h>

#define E_   3072
#define D_   128
#define H_   8
#define HD_  16
#define R_   64
#define FF_  512
#define L_   3
#define CAP_ 128

// ---------------- scratch (no allocations allowed) ----------------
#define OFF_H    0
#define OFF_Q    393216
#define OFF_K    786432
#define OFF_V    1179648
#define OFF_ATT  1572864
#define OFF_MID  2359296
#define OFF_RBF  3932160
#define OFF_PX   4128768
#define OFF_X    4137984
#define OFF_META 4147200
#define OFF_RBFW 4159488
#define TOTAL_F  4945920

__device__ __align__(16) float g_buf[TOTAL_F];
__device__ int g_ilist[E_ * CAP_];
__device__ int g_xlist[E_ * CAP_];
__device__ int g_icnt[E_];
__device__ int g_xcnt[E_];

// ---------------- packed f32x2 helpers (Blackwell FFMA2) ----------------
typedef unsigned long long ull;
__device__ __forceinline__ ull pack2(float lo, float hi) {
    ull r; asm("mov.b64 %0, {%1, %2};" : "=l"(r) : "f"(lo), "f"(hi)); return r;
}
__device__ __forceinline__ ull dup2(float v) {
    ull r; asm("mov.b64 %0, {%1, %1};" : "=l"(r) : "f"(v)); return r;
}
__device__ __forceinline__ ull fma2(ull a, ull b, ull c) {
    ull d; asm("fma.rn.f32x2 %0, %1, %2, %3;" : "=l"(d) : "l"(a), "l"(b), "l"(c)); return d;
}
__device__ __forceinline__ float2 unpk(ull v) {
    float lo, hi; asm("mov.b64 {%0, %1}, %2;" : "=f"(lo), "=f"(hi) : "l"(v));
    return make_float2(lo, hi);
}

// ---------------- prep: edge meta + rbf + zero px ----------------
__global__ void prep_kernel(const int* __restrict__ ei, const int* __restrict__ bid,
                            const float* __restrict__ nc, int4* __restrict__ meta,
                            float* __restrict__ rbf, float* __restrict__ px) {
    int e = blockIdx.x * 128 + threadIdx.x;
    if (e >= E_) return;
    int s = ei[e], d = ei[E_ + e];
    meta[e] = make_int4(s, d, bid[s], bid[d]);
    px[e*3+0] = 0.f; px[e*3+1] = 0.f; px[e*3+2] = 0.f;
    float dx = nc[d*3+0] - nc[s*3+0];
    float dy = nc[d*3+1] - nc[s*3+1];
    float dz = nc[d*3+2] - nc[s*3+2];
    float dist = sqrtf(dx*dx + dy*dy + dz*dz);
    float t = fminf(dist * 0.1f, 1.0f);
    float fc = 0.5f * (cosf(3.14159265358979323846f * t) + 1.0f);
    const float inw = 64.0f / 10.0f;   // 1/width, width = CUTOFF/R
    #pragma unroll 8
    for (int r = 0; r < R_; r++) {
        float c = 10.0f * (float)r / 63.0f;   // linspace(0,10,64)
        float u = (dist - c) * inw;
        rbf[e * R_ + r] = expf(-u * u) * fc;
    }
}

// ---------------- build neighbor lists (once; layer/head-invariant) ----------
__global__ void __launch_bounds__(128) build_kernel(const int4* __restrict__ meta) {
    __shared__ int ci, cx;
    int i = blockIdx.x, tid = threadIdx.x;
    if (tid == 0) { ci = 0; cx = 0; }
    __syncthreads();
    int4 mi = meta[i];
    for (int j = tid; j < E_; j += 128) {
        int4 mj = meta[j];
        bool ip = (mi.z == mj.z) && (mi.w == mj.w);
        bool share = (mi.x == mj.x) || (mi.x == mj.y) || (mi.y == mj.x) || (mi.y == mj.y);
        if (ip || (i == j)) {
            int p = atomicAdd(&ci, 1);
            if (p < CAP_) g_ilist[i * CAP_ + p] = j;
        }
        if ((share && !ip) || (i == j)) {
            int p = atomicAdd(&cx, 1);
            if (p < CAP_) g_xlist[i * CAP_ + p] = j;
        }
    }
    __syncthreads();
    if (tid == 0) {
        g_icnt[i] = min(ci, CAP_);
        g_xcnt[i] = min(cx, CAP_);
    }
}

// ---------------- utility ----------------
__global__ void copy_kernel(float* __restrict__ dst, const float* __restrict__ src, int n) {
    int i = blockIdx.x * 256 + threadIdx.x;
    if (i < n) dst[i] = src[i];
}

// ============ fused GEMM, tile 16x128, 256 threads, double-buffered, f32x2 ======
// Epilogues:
//   EPI 0: plain store; blockIdx.z selects B0/B1/B2, C = C0 + z*M*128  (QKV)
//   EPI 2: C = silu(A@B + bias)                                        (FFN up)
//   EPI 3: C = LN(res + A@B)*g + b                                     (attn o-proj)
//   EPI 4: t = LN(res + A@B + bias)*g + b; gate=tanh(t@Wc+bc);
//          x += gate*(x-px); px=0; C = t + extra (extra = rbfW of next layer)
//   EPI 5: z selects B; C = A@B (+res if z==0); z=0 -> C0, z>0 -> C12+(z-1)*M*128
// Warp ty owns rows m0+2ty, m0+2ty+1 across all 128 cols -> LN/gate = warp reduce.
template<int EPI>
__global__ void __launch_bounds__(256) gemm_kernel(
    const float* __restrict__ A, const float* __restrict__ B0,
    const float* __restrict__ B1, const float* __restrict__ B2,
    float* C0, float* C12, const float* res,
    int M, int K, int Ntot,
    const float* __restrict__ bias,
    const float* __restrict__ g, const float* __restrict__ b,
    const float* __restrict__ Wc, const float* __restrict__ bc,
    float* px, float* x, const float* __restrict__ extra)
{
    __shared__ __align__(16) float As[2][16 * 18];   // k-major, stride 18
    __shared__ __align__(16) float Bs[2][16][128];
    int z = blockIdx.z;
    const float* B = (z == 0) ? B0 : ((z == 1) ? B1 : B2);
    float* C;
    if (EPI == 0)      C = C0 + (size_t)z * M * 128;
    else if (EPI == 5) C = (z == 0) ? C0 : (C12 + (size_t)(z - 1) * M * 128);
    else               C = C0;

    int tid = threadIdx.x, tx = tid & 31, ty = tid >> 5;
    int m0 = blockIdx.y << 4, cb = blockIdx.x << 7;
    int nt = K >> 4;

    int am = tid >> 2, ak = (tid & 3) << 2;              // A loaders: tid<64
    int br0 = tid >> 5, bcol = (tid & 31) << 2;          // B rows 0..7
    int br1 = br0 + 8;                                    // B rows 8..15

    // ---- prologue: tile 0 -> smem[0]
    float4 pa = make_float4(0.f,0.f,0.f,0.f);
    if (tid < 64) pa = *(const float4*)&A[(size_t)(m0 + am) * K + ak];
    float4 pb0 = *(const float4*)&B[(size_t)br0 * Ntot + cb + bcol];
    float4 pb1 = *(const float4*)&B[(size_t)br1 * Ntot + cb + bcol];
    if (tid < 64) {
        As[0][(ak + 0) * 18 + am] = pa.x;
        As[0][(ak + 1) * 18 + am] = pa.y;
        As[0][(ak + 2) * 18 + am] = pa.z;
        As[0][(ak + 3) * 18 + am] = pa.w;
    }
    *(float4*)&Bs[0][br0][bcol] = pb0;
    *(float4*)&Bs[0][br1][bcol] = pb1;
    __syncthreads();

    ull c2[4] = {0ULL, 0ULL, 0ULL, 0ULL};
    for (int t = 0; t < nt; t++) {
        int cur = t & 1;
        if (t + 1 < nt) {            // prefetch next tile to regs (overlaps compute)
            int k0 = (t + 1) << 4;
            if (tid < 64) pa = *(const float4*)&A[(size_t)(m0 + am) * K + k0 + ak];
            pb0 = *(const float4*)&B[(size_t)(k0 + br0) * Ntot + cb + bcol];
            pb1 = *(const float4*)&B[(size_t)(k0 + br1) * Ntot + cb + bcol];
        }
        #pragma unroll
        for (int k = 0; k < 16; k++) {
            float2 a  = *(const float2*)&As[cur][k * 18 + ty * 2];   // rows 2ty,2ty+1
            float4 bv = *(const float4*)&Bs[cur][k][tx << 2];
            ull Ap = pack2(a.x, a.y);
            c2[0] = fma2(Ap, dup2(bv.x), c2[0]);
            c2[1] = fma2(Ap, dup2(bv.y), c2[1]);
            c2[2] = fma2(Ap, dup2(bv.z), c2[2]);
            c2[3] = fma2(Ap, dup2(bv.w), c2[3]);
        }
        if (t + 1 < nt) {
            int nb = cur ^ 1;
            if (tid < 64) {
                As[nb][(ak + 0) * 18 + am] = pa.x;
                As[nb][(ak + 1) * 18 + am] = pa.y;
                As[nb][(ak + 2) * 18 + am] = pa.z;
                As[nb][(ak + 3) * 18 + am] = pa.w;
            }
            *(float4*)&Bs[nb][br0][bcol] = pb0;
            *(float4*)&Bs[nb][br1][bcol] = pb1;
        }
        __syncthreads();
    }

    float val[2][4];
    #pragma unroll
    for (int c = 0; c < 4; c++) {
        float2 u = unpk(c2[c]);
        val[0][c] = u.x;
        val[1][c] = u.y;
    }
    int cg = cb + (tx << 2);
    int r0 = m0 + ty * 2;

    if (EPI == 0) {
        #pragma unroll
        for (int i = 0; i < 2; i++)
            *(float4*)&C[(size_t)(r0 + i) * Ntot + cg] =
                make_float4(val[i][0], val[i][1], val[i][2], val[i][3]);
        return;
    }
    if (EPI == 5) {
        #pragma unroll
        for (int i = 0; i < 2; i++) {
            float4 o = make_float4(val[i][0], val[i][1], val[i][2], val[i][3]);
            if (z == 0) {
                float4 rv = *(const float4*)&res[(size_t)(r0 + i) * 128 + cg];
                o.x += rv.x; o.y += rv.y; o.z += rv.z; o.w += rv.w;
            }
            *(float4*)&C[(size_t)(r0 + i) * 128 + cg] = o;
        }
        return;
    }
    if (EPI == 2) {
        float4 bv = *(const float4*)&bias[cg];
        #pragma unroll
        for (int i = 0; i < 2; i++) {
            float v0 = val[i][0] + bv.x, v1 = val[i][1] + bv.y;
            float v2 = val[i][2] + bv.z, v3 = val[i][3] + bv.w;
            v0 = v0 / (1.0f + __expf(-v0));
            v1 = v1 / (1.0f + __expf(-v1));
            v2 = v2 / (1.0f + __expf(-v2));
            v3 = v3 / (1.0f + __expf(-v3));
            *(float4*)&C[(size_t)(r0 + i) * Ntot + cg] = make_float4(v0, v1, v2, v3);
        }
        return;
    }

    // EPI 3 / 4: residual (+bias), row LayerNorm
    float4 bv = make_float4(0.f, 0.f, 0.f, 0.f);
    if (EPI == 4) bv = *(const float4*)&bias[cg];
    #pragma unroll
    for (int i = 0; i < 2; i++) {
        float4 rv = *(const float4*)&res[(size_t)(r0 + i) * 128 + cg];
        val[i][0] += rv.x + bv.x;  val[i][1] += rv.y + bv.y;
        val[i][2] += rv.z + bv.z;  val[i][3] += rv.w + bv.w;
    }
    float s[2], sq[2];
    #pragma unroll
    for (int i = 0; i < 2; i++) {
        s[i]  = val[i][0] + val[i][1] + val[i][2] + val[i][3];
        sq[i] = val[i][0]*val[i][0] + val[i][1]*val[i][1]
              + val[i][2]*val[i][2] + val[i][3]*val[i][3];
    }
    #pragma unroll
    for (int o = 16; o > 0; o >>= 1) {
        #pragma unroll
        for (int i = 0; i < 2; i++) {
            s[i]  += __shfl_xor_sync(0xffffffffu, s[i],  o);
            sq[i] += __shfl_xor_sync(0xffffffffu, sq[i], o);
        }
    }
    float4 g4 = *(const float4*)&g[cg];
    float4 b4 = *(const float4*)&b[cg];
    float gd[2];
    float4 wc4 = make_float4(0.f, 0.f, 0.f, 0.f);
    if (EPI == 4) wc4 = *(const float4*)&Wc[cg];
    #pragma unroll
    for (int i = 0; i < 2; i++) {
        float mean = s[i] * (1.0f / 128.0f);
        float var  = fmaxf(sq[i] * (1.0f / 128.0f) - mean * mean, 0.0f);
        float rstd = rsqrtf(var + 1e-5f);
        float h0 = (val[i][0] - mean) * rstd * g4.x + b4.x;
        float h1 = (val[i][1] - mean) * rstd * g4.y + b4.y;
        float h2 = (val[i][2] - mean) * rstd * g4.z + b4.z;
        float h3 = (val[i][3] - mean) * rstd * g4.w + b4.w;
        if (EPI == 4) {
            gd[i] = h0*wc4.x + h1*wc4.y + h2*wc4.z + h3*wc4.w;
            if (extra) {
                float4 ev = *(const float4*)&extra[(size_t)(r0 + i) * 128 + cg];
                h0 += ev.x; h1 += ev.y; h2 += ev.z; h3 += ev.w;
            }
        }
        *(float4*)&C[(size_t)(r0 + i) * 128 + cg] = make_float4(h0, h1, h2, h3);
    }
    if (EPI == 4) {
        #pragma unroll
        for (int o = 16; o > 0; o >>= 1)
            #pragma unroll
            for (int i = 0; i < 2; i++)
                gd[i] += __shfl_xor_sync(0xffffffffu, gd[i], o);
        if (tx < 3) {
            float bcv = bc[0];
            #pragma unroll
            for (int i = 0; i < 2; i++) {
                int r = r0 + i;
                float gt = tanhf(gd[i] + bcv);
                float xv = x[r * 3 + tx];
                float pv = px[r * 3 + tx];
                x[r * 3 + tx]  = xv + gt * (xv - pv);
                px[r * 3 + tx] = 0.0f;   // ready for next layer / next replay
            }
        }
    }
}

// ---------------- sparse masked attention: one warp per (query, head) -----------
// Lanes split as (half, d): d = lane&15 is the head-dim, half = lane>>4 splits the
// neighbor list. Streaming softmax; halves merged via shfl at the end.
// In-loop shuffles use per-half masks (halves have different trip counts when n odd).
// INTRA also accumulates px[i] = mean_h sum_j p[h,i,j] * x[j] (atomicAdd, 3 lanes).
template<bool INTRA>
__global__ void __launch_bounds__(256) attn_kernel(
    const float* __restrict__ q, const float* __restrict__ k, const float* __restrict__ v,
    const float* __restrict__ x, float* __restrict__ out, float* __restrict__ px)
{
    int warp = threadIdx.x >> 5, lane = threadIdx.x & 31;
    int i = blockIdx.x * 8 + warp;
    int head = blockIdx.y;
    int off = head * HD_;
    int d = lane & 15, half = lane >> 4;
    unsigned hm = half ? 0xffff0000u : 0x0000ffffu;   // lanes of MY half only

    float qd = q[i * D_ + off + d];
    int n = INTRA ? g_icnt[i] : g_xcnt[i];
    const int* li = (INTRA ? g_ilist : g_xlist) + i * CAP_;

    float m = -1e30f, l = 0.0f, acc = 0.0f, ax = 0.0f;

    for (int t = half; t < n; t += 2) {
        int j = li[t];
        float s = qd * k[j * D_ + off + d];
        s += __shfl_xor_sync(hm, s, 8);
        s += __shfl_xor_sync(hm, s, 4);
        s += __shfl_xor_sync(hm, s, 2);
        s += __shfl_xor_sync(hm, s, 1);
        s *= 0.25f;  // 1/sqrt(16)
        float vd = v[j * D_ + off + d];
        float mn = fmaxf(m, s);
        float cc = __expf(m - mn), p = __expf(s - mn);
        l = l * cc + p;
        acc = acc * cc + p * vd;
        if (INTRA && d < 3) ax = ax * cc + p * x[j * 3 + d];
        m = mn;
    }

    // merge the two halves (all 32 lanes re-converged -> full mask legal)
    float m2 = __shfl_xor_sync(0xffffffffu, m, 16);
    float l2 = __shfl_xor_sync(0xffffffffu, l, 16);
    float a2 = __shfl_xor_sync(0xffffffffu, acc, 16);
    float mn = fmaxf(m, m2);
    float c1 = __expf(m - mn), c2 = __expf(m2 - mn);
    l = l * c1 + l2 * c2;
    acc = acc * c1 + a2 * c2;
    if (INTRA) {
        float x2 = __shfl_xor_sync(0xffffffffu, ax, 16);
        ax = ax * c1 + x2 * c2;
    }
    float inv = 1.0f / l;  // diag always present -> l > 0
    if (half == 0) {
        out[i * D_ + off + d] = acc * inv;
        if (INTRA && d < 3) atomicAdd(&px[i * 3 + d], ax * inv * 0.125f);
    }
}

// ---------------- output: concat(h, x) ----------------
__global__ void out_kernel(const float* __restrict__ h, const float* __restrict__ x,
                           float* __restrict__ out, int out_size)
{
    int i = blockIdx.x * 256 + threadIdx.x;
    if (i >= out_size) return;
    if (i < E_ * D_)               out[i] = h[i];
    else if (i < E_ * D_ + E_ * 3) out[i] = x[i - E_ * D_];
    else                           out[i] = 0.0f;
}

// ---------------- host ----------------
extern "C" void kernel_launch(void* const* d_in, const int* in_sizes, int n_in,
                              void* d_out, int out_size)
{
    const float* edge_features = (const float*)d_in[0];
    const float* edge_coords   = (const float*)d_in[1];
    const int*   edge_index    = (const int*)  d_in[2];
    const float* node_coords   = (const float*)d_in[3];
    const int*   block_ids     = (const int*)  d_in[4];
    const float* Wq_a = (const float*)d_in[5];
    const float* Wk_a = (const float*)d_in[6];
    const float* Wv_a = (const float*)d_in[7];
    const float* Wo_a = (const float*)d_in[8];
    const float* Wq_e = (const float*)d_in[9];
    const float* Wk_e = (const float*)d_in[10];
    const float* Wv_e = (const float*)d_in[11];
    const float* Wo_e = (const float*)d_in[12];
    const float* W1   = (const float*)d_in[13];
    const float* b1   = (const float*)d_in[14];
    const float* W2   = (const float*)d_in[15];
    const float* b2   = (const float*)d_in[16];
    const float* ln1g = (const float*)d_in[17];
    const float* ln1b = (const float*)d_in[18];
    const float* ln2g = (const float*)d_in[19];
    const float* ln2b = (const float*)d_in[20];
    const float* ln3g = (const float*)d_in[21];
    const float* ln3b = (const float*)d_in[22];
    const float* Wrbf = (const float*)d_in[23];
    const float* Wc   = (const float*)d_in[24];
    const float* bc   = (const float*)d_in[25];

    float* buf = nullptr;
    cudaGetSymbolAddress((void**)&buf, g_buf);
    float* h    = buf + OFF_H;
    float* qb   = buf + OFF_Q;     // q,k,v contiguous -> batched GEMM dst
    float* kb   = buf + OFF_K;
    float* vb   = buf + OFF_V;
    float* att  = buf + OFF_ATT;
    float* mid  = buf + OFF_MID;
    float* rbf  = buf + OFF_RBF;
    float* px   = buf + OFF_PX;
    float* xb   = buf + OFF_X;
    int4*  meta = (int4*)(buf + OFF_META);
    float* rbfW = buf + OFF_RBFW;  // rbfW for layers 1,2 (layer 0 goes into h)

    dim3 g1(1, E_ / 16, 1);    // 192 blocks
    dim3 g3(1, E_ / 16, 3);    // 576 blocks
    dim3 gF(FF_ / 128, E_ / 16, 1);  // 768 blocks
    dim3 gAttn(E_ / 8, H_);

    prep_kernel<<<(E_ + 127) / 128, 128>>>(edge_index, block_ids, node_coords, meta, rbf, px);
    build_kernel<<<E_, 128>>>(meta);
    copy_kernel<<<(E_ * 3 + 255) / 256, 256>>>(xb, edge_coords, E_ * 3);

    // rbfW_l = rbf @ Wrbf[l] for all 3 layers in one launch.
    // z=0 -> h = edge_features + rbfW_0 (layer-0 h'); z=1,2 -> rbfW buffers.
    gemm_kernel<5><<<g3, 256>>>(rbf, Wrbf, Wrbf + R_ * D_, Wrbf + 2 * R_ * D_,
                                h, rbfW, edge_features, E_, R_, D_,
                                nullptr, nullptr, nullptr, nullptr, nullptr,
                                nullptr, nullptr, nullptr);

    for (int l = 0; l < L_; l++) {
        const int DD = D_ * D_;
        const float* nextRbfW = (l < 2) ? (rbfW + (size_t)l * E_ * D_) : nullptr;

        // --- intra attention ---
        gemm_kernel<0><<<g3, 256>>>(h, Wq_a + l * DD, Wk_a + l * DD, Wv_a + l * DD,
                                    qb, nullptr, nullptr, E_, D_, D_,
                                    nullptr, nullptr, nullptr, nullptr, nullptr,
                                    nullptr, nullptr, nullptr);
        attn_kernel<true><<<gAttn, 256>>>(qb, kb, vb, xb, att, px);
        gemm_kernel<3><<<g1, 256>>>(att, Wo_a + l * DD, nullptr, nullptr,
                                    h, nullptr, h, E_, D_, D_,
                                    nullptr, ln1g + l * D_, ln1b + l * D_,
                                    nullptr, nullptr, nullptr, nullptr, nullptr);

        // --- inter attention ---
        gemm_kernel<0><<<g3, 256>>>(h, Wq_e + l * DD, Wk_e + l * DD, Wv_e + l * DD,
                                    qb, nullptr, nullptr, E_, D_, D_,
                                    nullptr, nullptr, nullptr, nullptr, nullptr,
                                    nullptr, nullptr, nullptr);
        attn_kernel<false><<<gAttn, 256>>>(qb, kb, vb, xb, att, nullptr);
        gemm_kernel<3><<<g1, 256>>>(att, Wo_e + l * DD, nullptr, nullptr,
                                    h, nullptr, h, E_, D_, D_,
                                    nullptr, ln2g + l * D_, ln2b + l * D_,
                                    nullptr, nullptr, nullptr, nullptr, nullptr);

        // --- FFN (down-proj fuses residual+bias+LN+gate+x-update + next-layer rbf add)
        gemm_kernel<2><<<gF, 256>>>(h, W1 + l * D_ * FF_, nullptr, nullptr,
                                    mid, nullptr, nullptr, E_, D_, FF_,
                                    b1 + l * FF_, nullptr, nullptr,
                                    nullptr, nullptr, nullptr, nullptr, nullptr);
        gemm_kernel<4><<<g1, 256>>>(mid, W2 + l * FF_ * D_, nullptr, nullptr,
                                    h, nullptr, h, E_, FF_, D_,
                                    b2 + l * D_, ln3g + l * D_, ln3b + l * D_,
                                    Wc + l * D_, bc + l, px, xb, nextRbfW);
    }

    out_kernel<<<(out_size + 255) / 256, 256>>>(h, xb, (float*)d_out, out_size);
}